// round 2
// baseline (speedup 1.0000x reference)
#include <cuda_runtime.h>
#include <cstdint>
#include <cstddef>

#define PI_F 3.14159265358979323846f
#define FFT_M 32768

// ---- static scratch (device globals; no allocs allowed) ----
__device__ float  g_h1[64u*64u*8192u];
__device__ float  g_h2[64u*128u*4096u];
__device__ float  g_h3[64u*256u*2048u];
__device__ float2 g_fftA[128u*32768u];
__device__ float2 g_fftB[128u*32768u];
__device__ float2 g_tw[32768];
__device__ float  g_spec[64u*8448u];
__device__ float  g_spectrum[64u*256u];
__device__ float  g_timevec[64u*256u];
__device__ float  g_freqvec[64u*128u];

// =============== conv1: 1->64, k=7, +BN+relu+pool2 (one channel per block) ===============
__global__ void conv1_kernel(const float* __restrict__ x, const float* __restrict__ w,
                             const float* __restrict__ cb, const float* __restrict__ g,
                             const float* __restrict__ be, const float* __restrict__ m,
                             const float* __restrict__ v)
{
    __shared__ float sx[519];
    int tid = threadIdx.x;                    // 256
    int pb  = blockIdx.x * 256;               // pooled base (0..8191 step 256)
    int c   = blockIdx.y;
    int b   = blockIdx.z;
    const float* xb = x + (size_t)b * 16384;
    for (int idx = tid; idx < 519; idx += 256) {
        int t = 2*pb - 3 + idx;
        sx[idx] = (t >= 0 && t < 16384) ? xb[t] : 0.f;
    }
    float wv[7];
    #pragma unroll
    for (int j = 0; j < 7; j++) wv[j] = __ldg(w + c*7 + j);
    float sc = g[c] * rsqrtf(v[c] + 1e-5f);
    float sh = be[c] - m[c]*sc + cb[c]*sc;
    __syncthreads();
    float y0 = 0.f, y1 = 0.f;
    #pragma unroll
    for (int j = 0; j < 7; j++) {
        y0 = fmaf(wv[j], sx[2*tid + j],     y0);
        y1 = fmaf(wv[j], sx[2*tid + 1 + j], y1);
    }
    float r = fmaxf(fmaxf(y0*sc + sh, y1*sc + sh), 0.f);
    g_h1[((size_t)b*64 + c)*8192 + pb + tid] = r;
}

// =============== conv blocks 2/3: k=5, +BN+relu+pool2 ===============
// WHICH=0: g_h1(64ch,8192) -> g_h2(128ch,4096).  WHICH=1: g_h2 -> g_h3(256ch,2048).
template<int CIN, int COUT, int LIN, int WHICH>
__global__ void __launch_bounds__(COUT)
convblock_kernel(const float* __restrict__ w, const float* __restrict__ cb,
                 const float* __restrict__ g, const float* __restrict__ be,
                 const float* __restrict__ m, const float* __restrict__ v)
{
    const float* in = WHICH ? g_h2 : g_h1;
    float* out      = WHICH ? g_h3 : g_h2;
    const int LOUT = LIN / 2;
    __shared__ __align__(16) float sIn[CIN*36];
    int o  = threadIdx.x;                     // output channel
    int b  = blockIdx.y;
    int pb = blockIdx.x * 16;                 // 16 pooled outputs per block
    int ib = 2*pb - 2;
    const float* inb = in + (size_t)b * CIN * LIN;
    for (int idx = o; idx < CIN*36; idx += COUT) {
        int c = idx / 36, u = idx - c*36;
        int t = ib + u;
        sIn[idx] = (t >= 0 && t < LIN) ? inb[(size_t)c*LIN + t] : 0.f;
    }
    __syncthreads();

    float acc[32];
    #pragma unroll
    for (int q = 0; q < 32; q++) acc[q] = 0.f;
    const float* wbase = w + (size_t)o * CIN * 5;
    for (int c = 0; c < CIN; c++) {
        float wv[5];
        #pragma unroll
        for (int j = 0; j < 5; j++) wv[j] = wbase[c*5 + j];
        const float4* row4 = (const float4*)(sIn + c*36);
        float4 v0 = row4[0];
        #pragma unroll
        for (int t = 0; t < 8; t++) {
            float4 v1 = row4[t+1];
            float x8[8] = {v0.x, v0.y, v0.z, v0.w, v1.x, v1.y, v1.z, v1.w};
            #pragma unroll
            for (int dq = 0; dq < 4; dq++)
                #pragma unroll
                for (int j = 0; j < 5; j++)
                    acc[4*t + dq] = fmaf(wv[j], x8[dq + j], acc[4*t + dq]);
            v0 = v1;
        }
    }
    float sc = g[o] * rsqrtf(v[o] + 1e-5f);
    float sh = be[o] - m[o]*sc + cb[o]*sc;
    float r[16];
    #pragma unroll
    for (int p = 0; p < 16; p++) {
        float a0 = fmaxf(acc[2*p]*sc + sh, 0.f);
        float a1 = fmaxf(acc[2*p+1]*sc + sh, 0.f);
        r[p] = fmaxf(a0, a1);
    }
    float4* op = (float4*)(out + ((size_t)b*COUT + o)*LOUT + pb);
    #pragma unroll
    for (int p = 0; p < 4; p++)
        op[p] = make_float4(r[4*p], r[4*p+1], r[4*p+2], r[4*p+3]);
}

// =============== masked global average over time ===============
__global__ void timepool_kernel(const int* __restrict__ lengths)
{
    int c = blockIdx.x, b = blockIdx.y, tid = threadIdx.x; // 128
    int plen = lengths[b] >> 3; if (plen < 1) plen = 1;
    const float* p = g_h3 + ((size_t)b*256 + c)*2048;
    float s = 0.f;
    for (int t = tid; t < plen; t += 128) s += p[t];
    __shared__ float red[4];
    #pragma unroll
    for (int off = 16; off; off >>= 1) s += __shfl_down_sync(0xffffffffu, s, off);
    if ((tid & 31) == 0) red[tid >> 5] = s;
    __syncthreads();
    if (tid == 0) g_timevec[b*256 + c] = (red[0]+red[1]+red[2]+red[3]) / (float)plen;
}

// =============== FFT: Bluestein with M=32768 Stockham radix-2 ===============
__global__ void fft_twiddle_kernel()
{
    int p = blockIdx.x*blockDim.x + threadIdx.x;  // 0..16383
    int off = 0;
    #pragma unroll
    for (int st = 0; st < 15; st++) {
        int n = FFT_M >> st, mm = n >> 1;
        if (p < mm) {
            float sv, cv; sincosf(-2.f*PI_F*(float)p/(float)n, &sv, &cv);
            g_tw[off + p] = make_float2(cv, sv);
        }
        off += mm;
    }
}

__global__ void fft_build_kernel(const float* __restrict__ x, const int* __restrict__ lengths)
{
    int n = blockIdx.x*blockDim.x + threadIdx.x;  // 0..32767
    int i = blockIdx.y;
    int L = lengths[i];
    int mm = (n <= FFT_M - n) ? n : FFT_M - n;
    float2 a  = make_float2(0.f, 0.f);
    float2 bb = make_float2(0.f, 0.f);
    if (mm < L) {
        unsigned r = ((unsigned)mm * (unsigned)mm) % (unsigned)(2*L);
        float sv, cv; sincosf(PI_F * (float)r / (float)L, &sv, &cv);
        bb = make_float2(cv, sv);                 // chirp b[n]=e^{+i pi n^2/L}
        if (n < L) {
            float xv = x[(size_t)i*16384 + n];
            a = make_float2(xv*cv, -xv*sv);       // x[n]*conj(b[n])
        }
    }
    g_fftA[(size_t)i*FFT_M + n]      = a;
    g_fftA[(size_t)(64+i)*FFT_M + n] = bb;
}

__global__ void fft_stage_kernel(int sel, int sShift, int twOff)
{
    const float2* __restrict__ src = sel ? g_fftB : g_fftA;
    float2* __restrict__ dst       = sel ? g_fftA : g_fftB;
    int i = blockIdx.x*blockDim.x + threadIdx.x;  // butterfly 0..16383
    size_t base = (size_t)blockIdx.y * FFT_M;
    float2 a = src[base + i];
    float2 b = src[base + i + FFT_M/2];
    int p = i >> sShift;
    int s = 1 << sShift;
    float2 w = g_tw[twOff + p];
    float dx = a.x - b.x, dy = a.y - b.y;
    int j = i + p*s;
    dst[base + j]     = make_float2(a.x + b.x, a.y + b.y);
    dst[base + j + s] = make_float2(fmaf(dx, w.x, -dy*w.y), fmaf(dx, w.y, dy*w.x));
}

__global__ void fft_pointwise_kernel()   // C = conj(Ahat*Bhat) (inverse via conj trick)
{
    int n = blockIdx.x*blockDim.x + threadIdx.x;
    int i = blockIdx.y;
    float2 A = g_fftB[(size_t)i*FFT_M + n];
    float2 B = g_fftB[(size_t)(64+i)*FFT_M + n];
    g_fftA[(size_t)i*FFT_M + n] =
        make_float2(A.x*B.x - A.y*B.y, -(A.x*B.y + A.y*B.x));
}

__global__ void fft_finalize_kernel(const int* __restrict__ lengths)
{
    int k = blockIdx.x*blockDim.x + threadIdx.x;
    int i = blockIdx.y;
    int K = lengths[i]/2 + 1;
    if (k < K) {
        float2 c = g_fftB[(size_t)i*FFT_M + k];
        g_spec[(size_t)i*8448 + k] = log1pf(sqrtf(c.x*c.x + c.y*c.y) * (1.0f/32768.0f));
    }
}

__global__ void apool_kernel(const int* __restrict__ lengths)  // exact adaptive_avg_pool1d
{
    int i = blockIdx.x, j = threadIdx.x;          // 256 bins
    int K = lengths[i]/2 + 1;
    int s0 = (j*K) >> 8;
    int e0 = ((j+1)*K + 255) >> 8;
    const float* sp = g_spec + (size_t)i*8448;
    float s = 0.f;
    for (int t = s0; t < e0; t++) s += sp[t];
    g_spectrum[i*256 + j] = s / (float)(e0 - s0);
}

// =============== small GEMMs ===============
__global__ void freqlin_kernel(const float* __restrict__ fw, const float* __restrict__ fb)
{
    int i = blockIdx.x, h = threadIdx.x;          // 128
    __shared__ float sp[256];
    for (int f = h; f < 256; f += 128) sp[f] = g_spectrum[i*256 + f];
    __syncthreads();
    float acc = fb[h];
    const float* wr = fw + (size_t)h*256;
    for (int f = 0; f < 256; f++) acc = fmaf(sp[f], wr[f], acc);
    g_freqvec[i*128 + h] = fmaxf(acc, 0.f);
}

__global__ void head_kernel(const float* __restrict__ w0, const float* __restrict__ b0,
                            const float* __restrict__ w1, const float* __restrict__ b1,
                            float* __restrict__ out)
{
    int b = blockIdx.x, tid = threadIdx.x;        // 128
    __shared__ float fused[384];
    __shared__ float hid[128];
    for (int j = tid; j < 384; j += 128)
        fused[j] = (j < 256) ? g_timevec[b*256 + j] : g_freqvec[b*128 + (j - 256)];
    __syncthreads();
    float acc = b0[tid];
    const float* wr = w0 + (size_t)tid*384;
    for (int j = 0; j < 384; j++) acc = fmaf(fused[j], wr[j], acc);
    hid[tid] = fmaxf(acc, 0.f);
    __syncthreads();
    int wid = tid >> 5, lane = tid & 31;          // 4 warps -> 4 classes
    float s = 0.f;
    for (int t = lane; t < 128; t += 32) s += hid[t] * w1[wid*128 + t];
    #pragma unroll
    for (int off = 16; off; off >>= 1) s += __shfl_down_sync(0xffffffffu, s, off);
    if (lane == 0) out[b*4 + wid] = s + b1[wid];
}

// =============== launch ===============
extern "C" void kernel_launch(void* const* d_in, const int* in_sizes, int n_in,
                              void* d_out, int out_size)
{
    const float* x   = (const float*)d_in[0];
    const int*   len = (const int*)  d_in[1];
    const float *cw0 = (const float*)d_in[2],  *cb0 = (const float*)d_in[3];
    const float *g0  = (const float*)d_in[4],  *be0 = (const float*)d_in[5];
    const float *m0  = (const float*)d_in[6],  *v0  = (const float*)d_in[7];
    const float *cw1 = (const float*)d_in[8],  *cb1 = (const float*)d_in[9];
    const float *g1  = (const float*)d_in[10], *be1 = (const float*)d_in[11];
    const float *m1  = (const float*)d_in[12], *v1  = (const float*)d_in[13];
    const float *cw2 = (const float*)d_in[14], *cb2 = (const float*)d_in[15];
    const float *g2  = (const float*)d_in[16], *be2 = (const float*)d_in[17];
    const float *m2  = (const float*)d_in[18], *v2  = (const float*)d_in[19];
    const float *fw  = (const float*)d_in[20], *fb  = (const float*)d_in[21];
    const float *hw0 = (const float*)d_in[22], *hb0 = (const float*)d_in[23];
    const float *hw1 = (const float*)d_in[24], *hb1 = (const float*)d_in[25];
    float* out = (float*)d_out;

    // time branch
    conv1_kernel<<<dim3(32,64,64), 256>>>(x, cw0, cb0, g0, be0, m0, v0);
    convblock_kernel<64,128,8192,0><<<dim3(256,64), 128>>>(cw1, cb1, g1, be1, m1, v1);
    convblock_kernel<128,256,4096,1><<<dim3(128,64), 256>>>(cw2, cb2, g2, be2, m2, v2);
    timepool_kernel<<<dim3(256,64), 128>>>(len);

    // frequency branch
    fft_twiddle_kernel<<<64, 256>>>();
    fft_build_kernel<<<dim3(128,64), 256>>>(x, len);
    int sel = 0;
    for (int st = 0; st < 15; st++) {                    // forward FFT of A and chirp (batch 128)
        int twOff = 32768 - (32768 >> st);
        fft_stage_kernel<<<dim3(64,128), 256>>>(sel, st, twOff);
        sel ^= 1;
    }
    fft_pointwise_kernel<<<dim3(128,64), 256>>>();       // result in g_fftB -> C into g_fftA
    sel = 0;
    for (int st = 0; st < 15; st++) {                    // inverse FFT (forward of conj, batch 64)
        int twOff = 32768 - (32768 >> st);
        fft_stage_kernel<<<dim3(64,64), 256>>>(sel, st, twOff);
        sel ^= 1;
    }
    fft_finalize_kernel<<<dim3(33,64), 256>>>(len);
    apool_kernel<<<64, 256>>>(len);
    freqlin_kernel<<<64, 128>>>(fw, fb);

    // fuse + head
    head_kernel<<<64, 128>>>(hw0, hb0, hw1, hb1, out);
}